// round 12
// baseline (speedup 1.0000x reference)
#include <cuda_runtime.h>
#include <cuda_fp16.h>
#include <cstdint>
#include <cstddef>

// Problem constants
#define Bc 32
#define Sc 1024
#define Hc 1024
#define Wc 128
#define Kc 6
#define Lc (Bc*Wc)        // 4096 groups
#define Mc (Lc*Kc)        // 24576 max rows
#define Nc 2048           // q|k features
#define NTILES 192

// ---------------- static device scratch (allocation-free) ------------------
__device__ __align__(1024) __half g_A[(size_t)Mc * Hc];     // compacted A tiles
__device__ __align__(1024) __half g_W[(size_t)Nc * Hc];     // W tiles (paired q|k per head)
__device__ __align__(128)  __half g_biash[Nc];              // fp16 bias row
__device__ __align__(16)   __half g_xbuf[NTILES][6][Nc];    // crossing-group q|k rows
__device__ __align__(16)   float g_scores[(size_t)Lc * 16 * 36];  // per-group per-head scores
__device__ int g_len[Lc];
__device__ int g_start[Lc];
__device__ __align__(16) int g_rowsrc[Mc];                  // 16B-aligned: conv_a int4 loads
__device__ int g_tile_first[NTILES];
__device__ int g_tile_cnt[NTILES];
__device__ int g_cross[NTILES];
__device__ int g_Mv;

__device__ __forceinline__ uint32_t smem_u32(const void* p) {
    uint32_t a;
    asm("{ .reg .u64 t; cvta.to.shared.u64 t, %1; cvt.u32.u64 %0, t; }" : "=r"(a) : "l"(p));
    return a;
}

// ---------------- PTX wrappers -----------------------------------------
#define MBAR_INIT(addr, cnt) \
    asm volatile("mbarrier.init.shared.b64 [%0], %1;" :: "r"(addr), "r"(cnt) : "memory")
#define MBAR_EXPECT_TX(addr, bytes) \
    asm volatile("mbarrier.arrive.expect_tx.shared.b64 _, [%0], %1;" :: "r"(addr), "r"(bytes) : "memory")
#define MBAR_ARRIVE(addr) \
    asm volatile("mbarrier.arrive.shared.b64 _, [%0];" :: "r"(addr) : "memory")

__device__ __forceinline__ void mbar_wait(uint32_t mbar, uint32_t phase) {
    asm volatile(
        "{\n\t.reg .pred P;\n\t"
        "WL_%=:\n\t"
        "mbarrier.try_wait.parity.acquire.cta.shared::cta.b64 P, [%0], %1, 0x989680;\n\t"
        "@P bra.uni WD_%=;\n\t"
        "bra.uni WL_%=;\n\t"
        "WD_%=:\n\t}"
        :: "r"(mbar), "r"(phase) : "memory");
}

__device__ __forceinline__ void bulk_g2s(uint32_t dst, const void* src, uint32_t bytes, uint32_t mbar) {
    asm volatile(
        "cp.async.bulk.shared::cluster.global.mbarrier::complete_tx::bytes [%0], [%1], %2, [%3];"
        :: "r"(dst), "l"(src), "r"(bytes), "r"(mbar) : "memory");
}

#define LDMX4(r0, r1, r2, r3, addr) \
    asm volatile("ldmatrix.sync.aligned.m8n8.x4.shared.b16 {%0,%1,%2,%3}, [%4];" \
                 : "=r"(r0), "=r"(r1), "=r"(r2), "=r"(r3) : "r"(addr))

__device__ __forceinline__ void mma16816(float* c, const uint32_t* a, const uint32_t* b) {
    asm volatile(
        "mma.sync.aligned.m16n8k16.row.col.f32.f16.f16.f32 "
        "{%0,%1,%2,%3}, {%4,%5,%6,%7}, {%8,%9}, {%0,%1,%2,%3};\n"
        : "+f"(c[0]), "+f"(c[1]), "+f"(c[2]), "+f"(c[3])
        : "r"(a[0]), "r"(a[1]), "r"(a[2]), "r"(a[3]), "r"(b[0]), "r"(b[1]));
}

// swizzled byte offset within a [128 x 64B] tile for (row r, 16B-chunk c)
__device__ __forceinline__ uint32_t tswz(int r, int c) {
    return (uint32_t)(r * 64 + ((c ^ ((r >> 1) & 3)) << 4));
}

// ---------------------------------------------------------------------------
// scan: block 0 = lengths/starts/rowsrc/tile-metadata/Mv; block 1 = fp16 bias
// ---------------------------------------------------------------------------
__global__ __launch_bounds__(1024)
void scan_groups(const int* __restrict__ sidx, const float* __restrict__ bias)
{
    if (blockIdx.x == 1) {
        int t = threadIdx.x;
        if (t < 256) {
            const float4* bp = (const float4*)(bias + t * 8);
            float4 b0 = bp[0], b1 = bp[1];
            __half2 h[4];
            h[0] = __floats2half2_rn(b0.x, b0.y);
            h[1] = __floats2half2_rn(b0.z, b0.w);
            h[2] = __floats2half2_rn(b1.x, b1.y);
            h[3] = __floats2half2_rn(b1.z, b1.w);
            ((uint4*)g_biash)[t] = *(uint4*)h;
        }
        return;
    }
    __shared__ int warp_sums[32];
    const int tid = threadIdx.x;
    const int lane = tid & 31, wid = tid >> 5;

    if (tid < NTILES) {
        g_tile_first[tid] = 0x7fffffff;
        g_tile_cnt[tid] = 0;
        g_cross[tid] = -1;
    }

    int lens[4]; int local = 0;
    #pragma unroll
    for (int q = 0; q < 4; q++) {
        int g = tid * 4 + q;
        const int* p = sidx + g * 6;
        int len = 2;
        #pragma unroll
        for (int k = 2; k < 6; k++) len += (p[k] != 0);
        lens[q] = len; local += len;
    }
    int v = local;
    #pragma unroll
    for (int o = 1; o < 32; o <<= 1) {
        int t = __shfl_up_sync(~0u, v, o);
        if (lane >= o) v += t;
    }
    if (lane == 31) warp_sums[wid] = v;
    __syncthreads();
    if (wid == 0) {
        int s = warp_sums[lane];
        #pragma unroll
        for (int o = 1; o < 32; o <<= 1) {
            int t = __shfl_up_sync(~0u, s, o);
            if (lane >= o) s += t;
        }
        warp_sums[lane] = s;
    }
    __syncthreads();
    int base = v - local + (wid ? warp_sums[wid - 1] : 0);
    #pragma unroll
    for (int q = 0; q < 4; q++) {
        int g = tid * 4 + q;
        g_len[g] = lens[q];
        g_start[g] = base;
        int t0 = base >> 7;
        int tend = (base + lens[q] - 1) >> 7;
        atomicMin(&g_tile_first[t0], g);
        atomicAdd(&g_tile_cnt[t0], 1);
        if (tend != t0) g_cross[t0] = g;
        int b = g >> 7;
        const int* p = sidx + g * 6;
        for (int k = 0; k < lens[q]; k++) g_rowsrc[base + k] = b * Sc + p[k];
        base += lens[q];
    }
    if (tid == 0) g_Mv = warp_sums[31];
}

// ---------------------------------------------------------------------------
// conv_w: fp32 W -> fp16 tiled+swizzled g_W, PAIRED layout (q|k per head)
// ---------------------------------------------------------------------------
__global__ __launch_bounds__(128)
void conv_w(const float* __restrict__ wqk)
{
    int n = blockIdx.x;
    int tid = threadIdx.x;
    int c0 = tid * 8;
    int tile, r;
    if (n < 1024) { tile = n >> 6; r = n & 63; }
    else          { int m2 = n - 1024; tile = m2 >> 6; r = 64 + (m2 & 63); }
    int kt = tid >> 2, c = tid & 3;
    const float* src = wqk + (size_t)n * Hc + c0;
    float4 v0 = *(const float4*)src;
    float4 v1 = *(const float4*)(src + 4);
    __half2 h[4];
    h[0] = __floats2half2_rn(v0.x, v0.y);
    h[1] = __floats2half2_rn(v0.z, v0.w);
    h[2] = __floats2half2_rn(v1.x, v1.y);
    h[3] = __floats2half2_rn(v1.z, v1.w);
    char* dst = (char*)g_W + ((size_t)(tile * 32 + kt)) * 8192 + tswz(r, c);
    *(uint4*)dst = *(uint4*)h;
}

// ---------------------------------------------------------------------------
// conv_a: 4 rows per block, MLP=4, explicit int4 index load
// (g_rowsrc __align__(16); Mc%4==0 -> in-bounds).
// ---------------------------------------------------------------------------
__global__ __launch_bounds__(128)
void conv_a(const float* __restrict__ emb)
{
    int m0 = blockIdx.x * 4;
    int Mv = g_Mv;
    int Mpad = (Mv + 127) & ~127;
    if (m0 >= Mpad) return;
    int tid = threadIdx.x;
    int c0 = tid * 8;
    int kt = tid >> 2, c = tid & 3;

    int4 srcv = *(const int4*)&g_rowsrc[m0];
    int sr[4] = { srcv.x, srcv.y, srcv.z, srcv.w };

    float4 v0[4], v1[4];
    #pragma unroll
    for (int r4 = 0; r4 < 4; r4++) {
        const float* src = emb + (size_t)sr[r4] * Hc + c0;
        v0[r4] = *(const float4*)src;
        v1[r4] = *(const float4*)(src + 4);
    }
    #pragma unroll
    for (int r4 = 0; r4 < 4; r4++) {
        int m = m0 + r4;
        uint4 out = make_uint4(0u, 0u, 0u, 0u);
        if (m < Mv) {
            __half2 h[4];
            h[0] = __floats2half2_rn(v0[r4].x, v0[r4].y);
            h[1] = __floats2half2_rn(v0[r4].z, v0[r4].w);
            h[2] = __floats2half2_rn(v1[r4].x, v1[r4].y);
            h[3] = __floats2half2_rn(v1[r4].z, v1[r4].w);
            out = *(uint4*)h;
        }
        int mt = m >> 7, r = m & 127;
        char* dst = (char*)g_A + ((size_t)(mt * 32 + kt)) * 8192 + tswz(r, c);
        *(uint4*)dst = out;
    }
}

// ---------------------------------------------------------------------------
// GEMM + fused score epilogue. CTA (bx=head, by=m-tile).
// ---------------------------------------------------------------------------
#define A_STG 16384
#define B_STG 16384
#define STG_B (A_STG + B_STG)          // 32768
#define NSTG  3
#define NSTAGES_TOTAL 16               // K=1024 / BK=64
#define SMEM_TOT (NSTG*STG_B + 128)    // 98432
#define CSTRIDE 132

__global__ __launch_bounds__(256, 2)
void gemm_qk(const float* __restrict__ bias)
{
    const int by = blockIdx.y;
    if (by * 128 >= g_Mv) return;

    extern __shared__ char smem[];
    const uint32_t sb = smem_u32(smem);
    const uint32_t mb_full = sb + NSTG * STG_B;
    const uint32_t mb_free = mb_full + 32;

    const int tid = threadIdx.x;
    const int wid = tid >> 5, lane = tid & 31;
    const int bx = blockIdx.x;   // head 0..15

    if (tid == 0) {
        #pragma unroll
        for (int s = 0; s < NSTG; s++) {
            MBAR_INIT(mb_full + 8 * s, 1);
            MBAR_INIT(mb_free + 8 * s, 8);
        }
    }
    __syncthreads();

    const char* Abase = (const char*)g_A + (size_t)by * 32 * 8192;
    const char* Bbase = (const char*)g_W + (size_t)bx * 32 * 8192;

    if (tid == 0) {
        #pragma unroll
        for (int s = 0; s < NSTG; s++) {
            MBAR_EXPECT_TX(mb_full + 8 * s, STG_B);
            bulk_g2s(sb + s * STG_B,         Abase + (size_t)s * A_STG, A_STG, mb_full + 8 * s);
            bulk_g2s(sb + s * STG_B + A_STG, Bbase + (size_t)s * B_STG, B_STG, mb_full + 8 * s);
        }
    }

    const int warp_m = wid & 3;
    const int warp_n = wid >> 2;
    const int rA0 = warp_m * 32 + (lane & 15);
    const int rA1 = rA0 + 16;
    const uint32_t aoff0 = (uint32_t)(rA0 * 64); const int swA0 = (rA0 >> 1) & 3;
    const uint32_t aoff1 = (uint32_t)(rA1 * 64); const int swA1 = (rA1 >> 1) & 3;
    const int cidA = lane >> 4;
    const int rBb = warp_n * 64 + ((lane >> 4) & 1) * 8 + (lane & 7);
    const int cidB = (lane >> 3) & 1;
    uint32_t boff[4]; int swB[4];
    #pragma unroll
    for (int np = 0; np < 4; np++) {
        int r = rBb + np * 16;
        boff[np] = (uint32_t)(r * 64);
        swB[np] = (r >> 1) & 3;
    }

    float c[2][8][4];
    #pragma unroll
    for (int i = 0; i < 2; i++)
        #pragma unroll
        for (int j = 0; j < 8; j++)
            #pragma unroll
            for (int q = 0; q < 4; q++) c[i][j][q] = 0.f;

    for (int st = 0; st < NSTAGES_TOTAL; st++) {
        const int s = st % NSTG;
        const uint32_t ph = (st / NSTG) & 1;
        mbar_wait(mb_full + 8 * s, ph);

        const uint32_t Abs = sb + s * STG_B;
        const uint32_t Bbs = Abs + A_STG;
        #pragma unroll
        for (int t2 = 0; t2 < 2; t2++) {
            const uint32_t Ab = Abs + t2 * 8192;
            const uint32_t Bb = Bbs + t2 * 8192;
            #pragma unroll
            for (int ks = 0; ks < 2; ks++) {
                const int kc = ks * 2;
                uint32_t a0[4], a1[4], b[4][4];
                LDMX4(a0[0], a0[1], a0[2], a0[3], Ab + aoff0 + (((kc + cidA) ^ swA0) << 4));
                LDMX4(a1[0], a1[1], a1[2], a1[3], Ab + aoff1 + (((kc + cidA) ^ swA1) << 4));
                #pragma unroll
                for (int np = 0; np < 4; np++)
                    LDMX4(b[np][0], b[np][1], b[np][2], b[np][3],
                          Bb + boff[np] + (((kc + cidB) ^ swB[np]) << 4));
                #pragma unroll
                for (int nf = 0; nf < 8; nf++) {
                    mma16816(c[0][nf], a0, &b[nf >> 1][(nf & 1) * 2]);
                    mma16816(c[1][nf], a1, &b[nf >> 1][(nf & 1) * 2]);
                }
            }
        }
        if (lane == 0) MBAR_ARRIVE(mb_free + 8 * s);

        if (st + NSTG < NSTAGES_TOTAL && wid == (st & 7) && lane == 0) {
            mbar_wait(mb_free + 8 * s, ph);
            MBAR_EXPECT_TX(mb_full + 8 * s, STG_B);
            bulk_g2s(sb + s * STG_B,         Abase + (size_t)(st + NSTG) * A_STG, A_STG, mb_full + 8 * s);
            bulk_g2s(sb + s * STG_B + A_STG, Bbase + (size_t)(st + NSTG) * B_STG, B_STG, mb_full + 8 * s);
        }
    }

    // ---------------- fused epilogue ----------------
    __syncthreads();                 // done with pipeline buffers
    float* Cs = (float*)smem;        // [130][CSTRIDE] fp32; rows 128/129 = bias rows
    int* sgs = (int*)(smem + 130 * CSTRIDE * 4);
    int* sgl = sgs + 64;

    const int gid = lane >> 2, tig = lane & 3;
    {
        const float* bglob = (warp_n == 0) ? (bias + bx * 64) : (bias + 1024 + bx * 64);
        #pragma unroll
        for (int mf = 0; mf < 2; mf++) {
            #pragma unroll
            for (int nf = 0; nf < 8; nf++) {
                int row = warp_m * 32 + mf * 16 + gid;
                int col = warp_n * 64 + nf * 8 + tig * 2;
                int cin = nf * 8 + tig * 2;
                float2 bv = *(const float2*)&bglob[cin];
                Cs[row * CSTRIDE + col]           = c[mf][nf][0] + bv.x;
                Cs[row * CSTRIDE + col + 1]       = c[mf][nf][1] + bv.y;
                Cs[(row + 8) * CSTRIDE + col]     = c[mf][nf][2] + bv.x;
                Cs[(row + 8) * CSTRIDE + col + 1] = c[mf][nf][3] + bv.y;
            }
        }
    }
    if (tid < 64) {
        Cs[128 * CSTRIDE + tid]      = bias[bx * 64 + tid];          // q bias row
        Cs[129 * CSTRIDE + 64 + tid] = bias[1024 + bx * 64 + tid];   // k bias row
    }
    const int first = g_tile_first[by];
    const int cnt   = g_tile_cnt[by];
    if (tid < cnt) {
        int g = first + tid;
        sgs[tid] = g_start[g];
        sgl[tid] = g_len[g];
    }
    __syncthreads();

    // crossing-group row spill
    {
        int gin = (by > 0) ? g_cross[by - 1] : -1;
        if (gin >= 0) {
            int st = g_start[gin], ln = g_len[gin];
            int nr = st + ln - by * 128;
            int l0 = by * 128 - st;
            for (int ii = tid; ii < nr * 64; ii += 256) {
                int rr = ii >> 6, cc = ii & 63;
                __half* xr = g_xbuf[by - 1][l0 + rr];
                xr[bx * 64 + cc]        = __float2half(Cs[rr * CSTRIDE + cc]);
                xr[1024 + bx * 64 + cc] = __float2half(Cs[rr * CSTRIDE + 64 + cc]);
            }
        }
        int gout = g_cross[by];
        if (gout >= 0) {
            int st = g_start[gout];
            int nr = by * 128 + 128 - st;
            int base = st - by * 128;
            for (int ii = tid; ii < nr * 64; ii += 256) {
                int rr = ii >> 6, cc = ii & 63;
                __half* xr = g_xbuf[by][rr];
                xr[bx * 64 + cc]        = __float2half(Cs[(base + rr) * CSTRIDE + cc]);
                xr[1024 + bx * 64 + cc] = __float2half(Cs[(base + rr) * CSTRIDE + 64 + cc]);
            }
        }
    }

    // per-group 6x6 score dots (one scalar store per element)
    for (int idx = tid; idx < cnt * 36; idx += 256) {
        int gi = idx / 36, p = idx - gi * 36;
        int i = p / 6, j = p - i * 6;
        int st = sgs[gi], ln = sgl[gi];
        if (((st + ln - 1) >> 7) != by) continue;   // crossing: handled in attn_final
        int base = st - by * 128;
        const float* qr = Cs + ((i < ln) ? (base + i) : 128) * CSTRIDE;
        const float* kr = Cs + ((j < ln) ? (base + j) : 129) * CSTRIDE + 64;
        float acc = 0.f;
        #pragma unroll
        for (int cc = 0; cc < 64; cc++) acc = fmaf(qr[cc], kr[cc], acc);
        float mi = (i < ln) ? 1.0f : 0.0f;
        float mj = (j < ln) ? 1.0f : 0.0f;
        g_scores[((size_t)(first + gi) * 16 + bx) * 36 + p] = acc * 0.125f + mi * mj;
    }
}

// ---------------------------------------------------------------------------
// copy_zero: writes only rows with s%8 != 0
// ---------------------------------------------------------------------------
__global__ __launch_bounds__(256)
void copy_zero(const float* __restrict__ emb, const int* __restrict__ sidx,
               float* __restrict__ out)
{
    int row = blockIdx.x;
    int b = row >> 10;
    int s = row & 1023;
    int w = s >> 3;
    int k = s & 7;
    if (k == 0) return;
    int zero = 0;
    if (k < 6) {
        int iv = __ldg(&sidx[(b * Wc + w) * Kc + k]);
        zero = (iv != 0);
    }
    const float4* src = (const float4*)(emb + (size_t)row * Hc);
    float4* dst = (float4*)(out + (size_t)row * Hc);
    float4 v = src[threadIdx.x];
    if (zero) v = make_float4(0.f, 0.f, 0.f, 0.f);
    dst[threadIdx.x] = v;
}

// ---------------------------------------------------------------------------
// attn_final: per group. Non-crossing: precomputed scores; crossing: rebuild.
// ---------------------------------------------------------------------------
__global__ __launch_bounds__(128)
void attn_final(const float* __restrict__ emb, const int* __restrict__ sidx,
                float* __restrict__ out)
{
    __shared__ uint32_t sqk[6144];
    __shared__ float ssc[576];
    __shared__ float swm[64];
    __shared__ float scon[8];
    __shared__ float smask[8];
    __shared__ int sidxs[8];

    const int g = blockIdx.x;
    const int tid = threadIdx.x;
    const int ln = g_len[g];
    const int st = g_start[g];
    const bool cross = ((st >> 7) != ((st + ln - 1) >> 7));

    if (tid < 6) {
        sidxs[tid] = __ldg(&sidx[g * 6 + tid]);
        smask[tid] = (tid < ln) ? 1.0f : 0.0f;
    }

    if (!cross) {
        const float* sp = g_scores + (size_t)g * 16 * 36;
        for (int i = tid; i < 576; i += 128) ssc[i] = sp[i];
        __syncthreads();
    } else {
        int bnd = st >> 7;
        const uint4* bh = (const uint4*)g_biash;
        uint4* d4 = (uint4*)sqk;
        for (int i = tid; i < 1536; i += 128) {
            int row = i >> 8;
            const uint4* src = (const uint4*)g_xbuf[bnd][row];
            d4[i] = (row < ln) ? src[i & 255] : bh[i & 255];
        }
        __syncthreads();
        for (int d0 = tid; d0 < 576; d0 += 128) {
            int h = d0 / 36; int p = d0 - h * 36; int i = p / 6; int j = p - i * 6;
            const uint32_t* qp = sqk + i * 1024 + h * 32;
            const uint32_t* kp = sqk + j * 1024 + 512 + h * 32;
            float acc = 0.f;
            #pragma unroll
            for (int dd = 0; dd < 32; dd++) {
                float2 q2 = __half22float2(*(const __half2*)&qp[dd]);
                float2 k2 = __half22float2(*(const __half2*)&kp[dd]);
                acc = fmaf(q2.x, k2.x, acc);
                acc = fmaf(q2.y, k2.y, acc);
            }
            ssc[d0] = acc * 0.125f + smask[i] * smask[j];
        }
        __syncthreads();
    }

    if (tid < 96) {
        float* r = ssc + tid * 6;
        float mx = r[0];
        #pragma unroll
        for (int j = 1; j < 6; j++) mx = fmaxf(mx, r[j]);
        float e[6]; float sum = 0.f;
        #pragma unroll
        for (int j = 0; j < 6; j++) { e[j] = expf(r[j] - mx); sum += e[j]; }
        float inv = 1.0f / sum;
        #pragma unroll
        for (int j = 0; j < 6; j++) r[j] = e[j] * inv;
    }
    __syncthreads();

    if (tid < 36) {
        float s = 0.f;
        #pragma unroll
        for (int h = 0; h < 16; h++) s += ssc[h * 36 + tid];
        swm[tid] = s * (1.0f / 16.0f);
    }
    __syncthreads();

    if (tid < 6) {
        float cj = 0.f;
        #pragma unroll
        for (int i = 0; i < 6; i++) cj += smask[i] * swm[i * 6 + tid];
        scon[tid] = cj * smask[tid];
    }
    __syncthreads();
    if (tid == 0) {
        float tot = 1e-8f;
        #pragma unroll
        for (int j = 0; j < 6; j++) tot += scon[j];
        float inv = 1.0f / tot;
        #pragma unroll
        for (int j = 0; j < 6; j++) scon[j] *= inv;
    }
    __syncthreads();

    int b = g >> 7;
    size_t baserow = (size_t)(b * Sc);
    float4* drow = (float4*)(out + (baserow + sidxs[0]) * (size_t)Hc);
    for (int c4 = tid; c4 < 256; c4 += 128) {
        float4 acc = make_float4(0.f, 0.f, 0.f, 0.f);
        #pragma unroll
        for (int k = 0; k < 6; k++) {
            float ck = scon[k];
            if (ck != 0.0f) {
                const float4 v =
                    ((const float4*)(emb + (baserow + sidxs[k]) * (size_t)Hc))[c4];
                acc.x += ck * v.x; acc.y += ck * v.y; acc.z += ck * v.z; acc.w += ck * v.w;
            }
        }
        drow[c4] = acc;
    }
}

// ---------------------------------------------------------------------------
extern "C" void kernel_launch(void* const* d_in, const int* in_sizes, int n_in,
                              void* d_out, int out_size)
{
    const float* emb  = (const float*)d_in[0];
    const float* wqk  = (const float*)d_in[1];
    const float* bias = (const float*)d_in[2];
    const int*   sidx = (const int*)d_in[3];
    float* out = (float*)d_out;

    static cudaStream_t s1 = nullptr, s2 = nullptr;
    static cudaEvent_t eFork = nullptr, eW = nullptr, eCA = nullptr, eCZ = nullptr;
    static bool ok = false;
    if (s1 == nullptr) {
        bool good = true;
        good &= (cudaStreamCreateWithFlags(&s1, cudaStreamNonBlocking) == cudaSuccess);
        good &= (cudaStreamCreateWithFlags(&s2, cudaStreamNonBlocking) == cudaSuccess);
        good &= (cudaEventCreateWithFlags(&eFork, cudaEventDisableTiming) == cudaSuccess);
        good &= (cudaEventCreateWithFlags(&eW, cudaEventDisableTiming) == cudaSuccess);
        good &= (cudaEventCreateWithFlags(&eCA, cudaEventDisableTiming) == cudaSuccess);
        good &= (cudaEventCreateWithFlags(&eCZ, cudaEventDisableTiming) == cudaSuccess);
        cudaFuncSetAttribute(gemm_qk, cudaFuncAttributeMaxDynamicSharedMemorySize, SMEM_TOT);
        ok = good;
    }

    if (ok) {
        cudaEventRecord(eFork, 0);
        // s1: conv_w early (GEMM's only other dependency)
        cudaStreamWaitEvent(s1, eFork, 0);
        conv_w<<<Nc, 128, 0, s1>>>(wqk);
        cudaEventRecord(eW, s1);

        // main: scan -> conv_a (runs with full DRAM bandwidth)
        scan_groups<<<2, 1024>>>(sidx, bias);
        conv_a<<<Mc / 4, 128>>>(emb);
        cudaEventRecord(eCA, 0);

        // s2: copy_zero AFTER conv_a -> hides under the GEMM's idle DRAM
        cudaStreamWaitEvent(s2, eCA, 0);
        copy_zero<<<Bc * Sc, 256, 0, s2>>>(emb, sidx, out);
        cudaEventRecord(eCZ, s2);

        // main: gemm (needs g_W) -> attn
        cudaStreamWaitEvent(0, eW, 0);
        dim3 gg(16, NTILES);
        gemm_qk<<<gg, 256, SMEM_TOT>>>(bias);

        attn_final<<<Lc, 128>>>(emb, sidx, out);
        cudaStreamWaitEvent(0, eCZ, 0);
    } else {
        // serial fallback
        conv_w<<<Nc, 128>>>(wqk);
        copy_zero<<<Bc * Sc, 256>>>(emb, sidx, out);
        scan_groups<<<2, 1024>>>(sidx, bias);
        conv_a<<<Mc / 4, 128>>>(emb);
        dim3 gg(16, NTILES);
        gemm_qk<<<gg, 256, SMEM_TOT>>>(bias);
        attn_final<<<Lc, 128>>>(emb, sidx, out);
    }
}

// round 13
// speedup vs baseline: 1.0592x; 1.0592x over previous
#include <cuda_runtime.h>
#include <cuda_fp16.h>
#include <cstdint>
#include <cstddef>

// Problem constants
#define Bc 32
#define Sc 1024
#define Hc 1024
#define Wc 128
#define Kc 6
#define Lc (Bc*Wc)        // 4096 groups
#define Mc (Lc*Kc)        // 24576 max rows
#define Nc 2048           // q|k features
#define NTILES 192

// ---------------- static device scratch (allocation-free) ------------------
__device__ __align__(1024) __half g_A[(size_t)Mc * Hc];     // compacted A tiles
__device__ __align__(1024) __half g_W[(size_t)Nc * Hc];     // W tiles (paired q|k per head)
__device__ __align__(128)  __half g_biash[Nc];              // fp16 bias row
__device__ __align__(16)   __half g_xbuf[NTILES][6][Nc];    // crossing-group q|k rows
__device__ __align__(16)   float g_scores[(size_t)Lc * 16 * 36];  // per-group per-head scores
__device__ int g_len[Lc];
__device__ int g_start[Lc];
__device__ __align__(16) int g_rowsrc[Mc];                  // 16B-aligned: conv_a int4 loads
__device__ int g_tile_first[NTILES];
__device__ int g_tile_cnt[NTILES];
__device__ int g_cross[NTILES];
__device__ int g_Mv;

__device__ __forceinline__ uint32_t smem_u32(const void* p) {
    uint32_t a;
    asm("{ .reg .u64 t; cvta.to.shared.u64 t, %1; cvt.u32.u64 %0, t; }" : "=r"(a) : "l"(p));
    return a;
}

// ---------------- PTX wrappers -----------------------------------------
#define MBAR_INIT(addr, cnt) \
    asm volatile("mbarrier.init.shared.b64 [%0], %1;" :: "r"(addr), "r"(cnt) : "memory")
#define MBAR_EXPECT_TX(addr, bytes) \
    asm volatile("mbarrier.arrive.expect_tx.shared.b64 _, [%0], %1;" :: "r"(addr), "r"(bytes) : "memory")
#define MBAR_ARRIVE(addr) \
    asm volatile("mbarrier.arrive.shared.b64 _, [%0];" :: "r"(addr) : "memory")

__device__ __forceinline__ void mbar_wait(uint32_t mbar, uint32_t phase) {
    asm volatile(
        "{\n\t.reg .pred P;\n\t"
        "WL_%=:\n\t"
        "mbarrier.try_wait.parity.acquire.cta.shared::cta.b64 P, [%0], %1, 0x989680;\n\t"
        "@P bra.uni WD_%=;\n\t"
        "bra.uni WL_%=;\n\t"
        "WD_%=:\n\t}"
        :: "r"(mbar), "r"(phase) : "memory");
}

__device__ __forceinline__ void bulk_g2s(uint32_t dst, const void* src, uint32_t bytes, uint32_t mbar) {
    asm volatile(
        "cp.async.bulk.shared::cluster.global.mbarrier::complete_tx::bytes [%0], [%1], %2, [%3];"
        :: "r"(dst), "l"(src), "r"(bytes), "r"(mbar) : "memory");
}

#define LDMX4(r0, r1, r2, r3, addr) \
    asm volatile("ldmatrix.sync.aligned.m8n8.x4.shared.b16 {%0,%1,%2,%3}, [%4];" \
                 : "=r"(r0), "=r"(r1), "=r"(r2), "=r"(r3) : "r"(addr))

__device__ __forceinline__ void mma16816(float* c, const uint32_t* a, const uint32_t* b) {
    asm volatile(
        "mma.sync.aligned.m16n8k16.row.col.f32.f16.f16.f32 "
        "{%0,%1,%2,%3}, {%4,%5,%6,%7}, {%8,%9}, {%0,%1,%2,%3};\n"
        : "+f"(c[0]), "+f"(c[1]), "+f"(c[2]), "+f"(c[3])
        : "r"(a[0]), "r"(a[1]), "r"(a[2]), "r"(a[3]), "r"(b[0]), "r"(b[1]));
}

// swizzled byte offset within a [128 x 64B] tile for (row r, 16B-chunk c)
__device__ __forceinline__ uint32_t tswz(int r, int c) {
    return (uint32_t)(r * 64 + ((c ^ ((r >> 1) & 3)) << 4));
}

// ---------------------------------------------------------------------------
// scan: block 0 = lengths/starts/rowsrc/tile-metadata/Mv; block 1 = fp16 bias
// ---------------------------------------------------------------------------
__global__ __launch_bounds__(1024)
void scan_groups(const int* __restrict__ sidx, const float* __restrict__ bias)
{
    if (blockIdx.x == 1) {
        int t = threadIdx.x;
        if (t < 256) {
            const float4* bp = (const float4*)(bias + t * 8);
            float4 b0 = bp[0], b1 = bp[1];
            __half2 h[4];
            h[0] = __floats2half2_rn(b0.x, b0.y);
            h[1] = __floats2half2_rn(b0.z, b0.w);
            h[2] = __floats2half2_rn(b1.x, b1.y);
            h[3] = __floats2half2_rn(b1.z, b1.w);
            ((uint4*)g_biash)[t] = *(uint4*)h;
        }
        return;
    }
    __shared__ int warp_sums[32];
    const int tid = threadIdx.x;
    const int lane = tid & 31, wid = tid >> 5;

    if (tid < NTILES) {
        g_tile_first[tid] = 0x7fffffff;
        g_tile_cnt[tid] = 0;
        g_cross[tid] = -1;
    }

    int lens[4]; int local = 0;
    #pragma unroll
    for (int q = 0; q < 4; q++) {
        int g = tid * 4 + q;
        const int* p = sidx + g * 6;
        int len = 2;
        #pragma unroll
        for (int k = 2; k < 6; k++) len += (p[k] != 0);
        lens[q] = len; local += len;
    }
    int v = local;
    #pragma unroll
    for (int o = 1; o < 32; o <<= 1) {
        int t = __shfl_up_sync(~0u, v, o);
        if (lane >= o) v += t;
    }
    if (lane == 31) warp_sums[wid] = v;
    __syncthreads();
    if (wid == 0) {
        int s = warp_sums[lane];
        #pragma unroll
        for (int o = 1; o < 32; o <<= 1) {
            int t = __shfl_up_sync(~0u, s, o);
            if (lane >= o) s += t;
        }
        warp_sums[lane] = s;
    }
    __syncthreads();
    int base = v - local + (wid ? warp_sums[wid - 1] : 0);
    #pragma unroll
    for (int q = 0; q < 4; q++) {
        int g = tid * 4 + q;
        g_len[g] = lens[q];
        g_start[g] = base;
        int t0 = base >> 7;
        int tend = (base + lens[q] - 1) >> 7;
        atomicMin(&g_tile_first[t0], g);
        atomicAdd(&g_tile_cnt[t0], 1);
        if (tend != t0) g_cross[t0] = g;
        int b = g >> 7;
        const int* p = sidx + g * 6;
        for (int k = 0; k < lens[q]; k++) g_rowsrc[base + k] = b * Sc + p[k];
        base += lens[q];
    }
    if (tid == 0) g_Mv = warp_sums[31];
}

// ---------------------------------------------------------------------------
// conv_w: fp32 W -> fp16 tiled+swizzled g_W, PAIRED layout (q|k per head)
// ---------------------------------------------------------------------------
__global__ __launch_bounds__(128)
void conv_w(const float* __restrict__ wqk)
{
    int n = blockIdx.x;
    int tid = threadIdx.x;
    int c0 = tid * 8;
    int tile, r;
    if (n < 1024) { tile = n >> 6; r = n & 63; }
    else          { int m2 = n - 1024; tile = m2 >> 6; r = 64 + (m2 & 63); }
    int kt = tid >> 2, c = tid & 3;
    const float* src = wqk + (size_t)n * Hc + c0;
    float4 v0 = *(const float4*)src;
    float4 v1 = *(const float4*)(src + 4);
    __half2 h[4];
    h[0] = __floats2half2_rn(v0.x, v0.y);
    h[1] = __floats2half2_rn(v0.z, v0.w);
    h[2] = __floats2half2_rn(v1.x, v1.y);
    h[3] = __floats2half2_rn(v1.z, v1.w);
    char* dst = (char*)g_W + ((size_t)(tile * 32 + kt)) * 8192 + tswz(r, c);
    *(uint4*)dst = *(uint4*)h;
}

// ---------------------------------------------------------------------------
// conv_a: 4 rows per block, MLP=4, explicit int4 index load
// (g_rowsrc __align__(16); Mc%4==0 -> in-bounds).
// ---------------------------------------------------------------------------
__global__ __launch_bounds__(128)
void conv_a(const float* __restrict__ emb)
{
    int m0 = blockIdx.x * 4;
    int Mv = g_Mv;
    int Mpad = (Mv + 127) & ~127;
    if (m0 >= Mpad) return;
    int tid = threadIdx.x;
    int c0 = tid * 8;
    int kt = tid >> 2, c = tid & 3;

    int4 srcv = *(const int4*)&g_rowsrc[m0];
    int sr[4] = { srcv.x, srcv.y, srcv.z, srcv.w };

    float4 v0[4], v1[4];
    #pragma unroll
    for (int r4 = 0; r4 < 4; r4++) {
        const float* src = emb + (size_t)sr[r4] * Hc + c0;
        v0[r4] = *(const float4*)src;
        v1[r4] = *(const float4*)(src + 4);
    }
    #pragma unroll
    for (int r4 = 0; r4 < 4; r4++) {
        int m = m0 + r4;
        uint4 out = make_uint4(0u, 0u, 0u, 0u);
        if (m < Mv) {
            __half2 h[4];
            h[0] = __floats2half2_rn(v0[r4].x, v0[r4].y);
            h[1] = __floats2half2_rn(v0[r4].z, v0[r4].w);
            h[2] = __floats2half2_rn(v1[r4].x, v1[r4].y);
            h[3] = __floats2half2_rn(v1[r4].z, v1[r4].w);
            out = *(uint4*)h;
        }
        int mt = m >> 7, r = m & 127;
        char* dst = (char*)g_A + ((size_t)(mt * 32 + kt)) * 8192 + tswz(r, c);
        *(uint4*)dst = out;
    }
}

// ---------------------------------------------------------------------------
// GEMM + fused score epilogue. CTA (bx=head, by=m-tile).
// ---------------------------------------------------------------------------
#define A_STG 16384
#define B_STG 16384
#define STG_B (A_STG + B_STG)          // 32768
#define NSTG  3
#define NSTAGES_TOTAL 16               // K=1024 / BK=64
#define SMEM_TOT (NSTG*STG_B + 128)    // 98432
#define CSTRIDE 132

__global__ __launch_bounds__(256, 2)
void gemm_qk(const float* __restrict__ bias)
{
    const int by = blockIdx.y;
    if (by * 128 >= g_Mv) return;

    extern __shared__ char smem[];
    const uint32_t sb = smem_u32(smem);
    const uint32_t mb_full = sb + NSTG * STG_B;
    const uint32_t mb_free = mb_full + 32;

    const int tid = threadIdx.x;
    const int wid = tid >> 5, lane = tid & 31;
    const int bx = blockIdx.x;   // head 0..15

    if (tid == 0) {
        #pragma unroll
        for (int s = 0; s < NSTG; s++) {
            MBAR_INIT(mb_full + 8 * s, 1);
            MBAR_INIT(mb_free + 8 * s, 8);
        }
    }
    __syncthreads();

    const char* Abase = (const char*)g_A + (size_t)by * 32 * 8192;
    const char* Bbase = (const char*)g_W + (size_t)bx * 32 * 8192;

    if (tid == 0) {
        #pragma unroll
        for (int s = 0; s < NSTG; s++) {
            MBAR_EXPECT_TX(mb_full + 8 * s, STG_B);
            bulk_g2s(sb + s * STG_B,         Abase + (size_t)s * A_STG, A_STG, mb_full + 8 * s);
            bulk_g2s(sb + s * STG_B + A_STG, Bbase + (size_t)s * B_STG, B_STG, mb_full + 8 * s);
        }
    }

    const int warp_m = wid & 3;
    const int warp_n = wid >> 2;
    const int rA0 = warp_m * 32 + (lane & 15);
    const int rA1 = rA0 + 16;
    const uint32_t aoff0 = (uint32_t)(rA0 * 64); const int swA0 = (rA0 >> 1) & 3;
    const uint32_t aoff1 = (uint32_t)(rA1 * 64); const int swA1 = (rA1 >> 1) & 3;
    const int cidA = lane >> 4;
    const int rBb = warp_n * 64 + ((lane >> 4) & 1) * 8 + (lane & 7);
    const int cidB = (lane >> 3) & 1;
    uint32_t boff[4]; int swB[4];
    #pragma unroll
    for (int np = 0; np < 4; np++) {
        int r = rBb + np * 16;
        boff[np] = (uint32_t)(r * 64);
        swB[np] = (r >> 1) & 3;
    }

    float c[2][8][4];
    #pragma unroll
    for (int i = 0; i < 2; i++)
        #pragma unroll
        for (int j = 0; j < 8; j++)
            #pragma unroll
            for (int q = 0; q < 4; q++) c[i][j][q] = 0.f;

    for (int st = 0; st < NSTAGES_TOTAL; st++) {
        const int s = st % NSTG;
        const uint32_t ph = (st / NSTG) & 1;
        mbar_wait(mb_full + 8 * s, ph);

        const uint32_t Abs = sb + s * STG_B;
        const uint32_t Bbs = Abs + A_STG;
        #pragma unroll
        for (int t2 = 0; t2 < 2; t2++) {
            const uint32_t Ab = Abs + t2 * 8192;
            const uint32_t Bb = Bbs + t2 * 8192;
            #pragma unroll
            for (int ks = 0; ks < 2; ks++) {
                const int kc = ks * 2;
                uint32_t a0[4], a1[4], b[4][4];
                LDMX4(a0[0], a0[1], a0[2], a0[3], Ab + aoff0 + (((kc + cidA) ^ swA0) << 4));
                LDMX4(a1[0], a1[1], a1[2], a1[3], Ab + aoff1 + (((kc + cidA) ^ swA1) << 4));
                #pragma unroll
                for (int np = 0; np < 4; np++)
                    LDMX4(b[np][0], b[np][1], b[np][2], b[np][3],
                          Bb + boff[np] + (((kc + cidB) ^ swB[np]) << 4));
                #pragma unroll
                for (int nf = 0; nf < 8; nf++) {
                    mma16816(c[0][nf], a0, &b[nf >> 1][(nf & 1) * 2]);
                    mma16816(c[1][nf], a1, &b[nf >> 1][(nf & 1) * 2]);
                }
            }
        }
        if (lane == 0) MBAR_ARRIVE(mb_free + 8 * s);

        if (st + NSTG < NSTAGES_TOTAL && wid == (st & 7) && lane == 0) {
            mbar_wait(mb_free + 8 * s, ph);
            MBAR_EXPECT_TX(mb_full + 8 * s, STG_B);
            bulk_g2s(sb + s * STG_B,         Abase + (size_t)(st + NSTG) * A_STG, A_STG, mb_full + 8 * s);
            bulk_g2s(sb + s * STG_B + A_STG, Bbase + (size_t)(st + NSTG) * B_STG, B_STG, mb_full + 8 * s);
        }
    }

    // ---------------- fused epilogue ----------------
    __syncthreads();                 // done with pipeline buffers
    float* Cs = (float*)smem;        // [130][CSTRIDE] fp32; rows 128/129 = bias rows
    int* sgs = (int*)(smem + 130 * CSTRIDE * 4);
    int* sgl = sgs + 64;

    const int gid = lane >> 2, tig = lane & 3;
    {
        const float* bglob = (warp_n == 0) ? (bias + bx * 64) : (bias + 1024 + bx * 64);
        #pragma unroll
        for (int mf = 0; mf < 2; mf++) {
            #pragma unroll
            for (int nf = 0; nf < 8; nf++) {
                int row = warp_m * 32 + mf * 16 + gid;
                int col = warp_n * 64 + nf * 8 + tig * 2;
                int cin = nf * 8 + tig * 2;
                float2 bv = *(const float2*)&bglob[cin];
                Cs[row * CSTRIDE + col]           = c[mf][nf][0] + bv.x;
                Cs[row * CSTRIDE + col + 1]       = c[mf][nf][1] + bv.y;
                Cs[(row + 8) * CSTRIDE + col]     = c[mf][nf][2] + bv.x;
                Cs[(row + 8) * CSTRIDE + col + 1] = c[mf][nf][3] + bv.y;
            }
        }
    }
    if (tid < 64) {
        Cs[128 * CSTRIDE + tid]      = bias[bx * 64 + tid];          // q bias row
        Cs[129 * CSTRIDE + 64 + tid] = bias[1024 + bx * 64 + tid];   // k bias row
    }
    const int first = g_tile_first[by];
    const int cnt   = g_tile_cnt[by];
    if (tid < cnt) {
        int g = first + tid;
        sgs[tid] = g_start[g];
        sgl[tid] = g_len[g];
    }
    __syncthreads();

    // crossing-group row spill
    {
        int gin = (by > 0) ? g_cross[by - 1] : -1;
        if (gin >= 0) {
            int st = g_start[gin], ln = g_len[gin];
            int nr = st + ln - by * 128;
            int l0 = by * 128 - st;
            for (int ii = tid; ii < nr * 64; ii += 256) {
                int rr = ii >> 6, cc = ii & 63;
                __half* xr = g_xbuf[by - 1][l0 + rr];
                xr[bx * 64 + cc]        = __float2half(Cs[rr * CSTRIDE + cc]);
                xr[1024 + bx * 64 + cc] = __float2half(Cs[rr * CSTRIDE + 64 + cc]);
            }
        }
        int gout = g_cross[by];
        if (gout >= 0) {
            int st = g_start[gout];
            int nr = by * 128 + 128 - st;
            int base = st - by * 128;
            for (int ii = tid; ii < nr * 64; ii += 256) {
                int rr = ii >> 6, cc = ii & 63;
                __half* xr = g_xbuf[by][rr];
                xr[bx * 64 + cc]        = __float2half(Cs[(base + rr) * CSTRIDE + cc]);
                xr[1024 + bx * 64 + cc] = __float2half(Cs[(base + rr) * CSTRIDE + 64 + cc]);
            }
        }
    }

    // per-group 6x6 score dots (one scalar store per element)
    for (int idx = tid; idx < cnt * 36; idx += 256) {
        int gi = idx / 36, p = idx - gi * 36;
        int i = p / 6, j = p - i * 6;
        int st = sgs[gi], ln = sgl[gi];
        if (((st + ln - 1) >> 7) != by) continue;   // crossing: handled in attn_final
        int base = st - by * 128;
        const float* qr = Cs + ((i < ln) ? (base + i) : 128) * CSTRIDE;
        const float* kr = Cs + ((j < ln) ? (base + j) : 129) * CSTRIDE + 64;
        float acc = 0.f;
        #pragma unroll
        for (int cc = 0; cc < 64; cc++) acc = fmaf(qr[cc], kr[cc], acc);
        float mi = (i < ln) ? 1.0f : 0.0f;
        float mj = (j < ln) ? 1.0f : 0.0f;
        g_scores[((size_t)(first + gi) * 16 + bx) * 36 + p] = acc * 0.125f + mi * mj;
    }
}

// ---------------------------------------------------------------------------
// copy_zero: writes only rows with s%8 != 0; zero rows skip the emb read
// ---------------------------------------------------------------------------
__global__ __launch_bounds__(256)
void copy_zero(const float* __restrict__ emb, const int* __restrict__ sidx,
               float* __restrict__ out)
{
    int row = blockIdx.x;
    int b = row >> 10;
    int s = row & 1023;
    int w = s >> 3;
    int k = s & 7;
    if (k == 0) return;
    int zero = 0;
    if (k < 6) {
        int iv = __ldg(&sidx[(b * Wc + w) * Kc + k]);
        zero = (iv != 0);
    }
    float4* dst = (float4*)(out + (size_t)row * Hc);
    float4 v = make_float4(0.f, 0.f, 0.f, 0.f);
    if (!zero) {
        const float4* src = (const float4*)(emb + (size_t)row * Hc);
        v = src[threadIdx.x];
    }
    dst[threadIdx.x] = v;
}

// ---------------------------------------------------------------------------
// attn_final: per group. Non-crossing: precomputed scores; crossing: rebuild.
// ---------------------------------------------------------------------------
__global__ __launch_bounds__(128)
void attn_final(const float* __restrict__ emb, const int* __restrict__ sidx,
                float* __restrict__ out)
{
    __shared__ uint32_t sqk[6144];
    __shared__ float ssc[576];
    __shared__ float swm[64];
    __shared__ float scon[8];
    __shared__ float smask[8];
    __shared__ int sidxs[8];

    const int g = blockIdx.x;
    const int tid = threadIdx.x;
    const int ln = g_len[g];
    const int st = g_start[g];
    const bool cross = ((st >> 7) != ((st + ln - 1) >> 7));

    if (tid < 6) {
        sidxs[tid] = __ldg(&sidx[g * 6 + tid]);
        smask[tid] = (tid < ln) ? 1.0f : 0.0f;
    }

    if (!cross) {
        const float* sp = g_scores + (size_t)g * 16 * 36;
        for (int i = tid; i < 576; i += 128) ssc[i] = sp[i];
        __syncthreads();
    } else {
        int bnd = st >> 7;
        const uint4* bh = (const uint4*)g_biash;
        uint4* d4 = (uint4*)sqk;
        for (int i = tid; i < 1536; i += 128) {
            int row = i >> 8;
            const uint4* src = (const uint4*)g_xbuf[bnd][row];
            d4[i] = (row < ln) ? src[i & 255] : bh[i & 255];
        }
        __syncthreads();
        for (int d0 = tid; d0 < 576; d0 += 128) {
            int h = d0 / 36; int p = d0 - h * 36; int i = p / 6; int j = p - i * 6;
            const uint32_t* qp = sqk + i * 1024 + h * 32;
            const uint32_t* kp = sqk + j * 1024 + 512 + h * 32;
            float acc = 0.f;
            #pragma unroll
            for (int dd = 0; dd < 32; dd++) {
                float2 q2 = __half22float2(*(const __half2*)&qp[dd]);
                float2 k2 = __half22float2(*(const __half2*)&kp[dd]);
                acc = fmaf(q2.x, k2.x, acc);
                acc = fmaf(q2.y, k2.y, acc);
            }
            ssc[d0] = acc * 0.125f + smask[i] * smask[j];
        }
        __syncthreads();
    }

    if (tid < 96) {
        float* r = ssc + tid * 6;
        float mx = r[0];
        #pragma unroll
        for (int j = 1; j < 6; j++) mx = fmaxf(mx, r[j]);
        float e[6]; float sum = 0.f;
        #pragma unroll
        for (int j = 0; j < 6; j++) { e[j] = expf(r[j] - mx); sum += e[j]; }
        float inv = 1.0f / sum;
        #pragma unroll
        for (int j = 0; j < 6; j++) r[j] = e[j] * inv;
    }
    __syncthreads();

    if (tid < 36) {
        float s = 0.f;
        #pragma unroll
        for (int h = 0; h < 16; h++) s += ssc[h * 36 + tid];
        swm[tid] = s * (1.0f / 16.0f);
    }
    __syncthreads();

    if (tid < 6) {
        float cj = 0.f;
        #pragma unroll
        for (int i = 0; i < 6; i++) cj += smask[i] * swm[i * 6 + tid];
        scon[tid] = cj * smask[tid];
    }
    __syncthreads();
    if (tid == 0) {
        float tot = 1e-8f;
        #pragma unroll
        for (int j = 0; j < 6; j++) tot += scon[j];
        float inv = 1.0f / tot;
        #pragma unroll
        for (int j = 0; j < 6; j++) scon[j] *= inv;
    }
    __syncthreads();

    int b = g >> 7;
    size_t baserow = (size_t)(b * Sc);
    float4* drow = (float4*)(out + (baserow + sidxs[0]) * (size_t)Hc);
    for (int c4 = tid; c4 < 256; c4 += 128) {
        float4 acc = make_float4(0.f, 0.f, 0.f, 0.f);
        #pragma unroll
        for (int k = 0; k < 6; k++) {
            float ck = scon[k];
            if (ck != 0.0f) {
                const float4 v =
                    ((const float4*)(emb + (baserow + sidxs[k]) * (size_t)Hc))[c4];
                acc.x += ck * v.x; acc.y += ck * v.y; acc.z += ck * v.z; acc.w += ck * v.w;
            }
        }
        drow[c4] = acc;
    }
}

// ---------------------------------------------------------------------------
extern "C" void kernel_launch(void* const* d_in, const int* in_sizes, int n_in,
                              void* d_out, int out_size)
{
    const float* emb  = (const float*)d_in[0];
    const float* wqk  = (const float*)d_in[1];
    const float* bias = (const float*)d_in[2];
    const int*   sidx = (const int*)d_in[3];
    float* out = (float*)d_out;

    static cudaStream_t s1 = nullptr;
    static cudaEvent_t eFork = nullptr, eW = nullptr, eJoin = nullptr;
    static bool ok = false;
    if (s1 == nullptr) {
        bool good = true;
        good &= (cudaStreamCreateWithFlags(&s1, cudaStreamNonBlocking) == cudaSuccess);
        good &= (cudaEventCreateWithFlags(&eFork, cudaEventDisableTiming) == cudaSuccess);
        good &= (cudaEventCreateWithFlags(&eW, cudaEventDisableTiming) == cudaSuccess);
        good &= (cudaEventCreateWithFlags(&eJoin, cudaEventDisableTiming) == cudaSuccess);
        cudaFuncSetAttribute(gemm_qk, cudaFuncAttributeMaxDynamicSharedMemorySize, SMEM_TOT);
        ok = good;
    }

    if (ok) {
        // R10 schedule (best known): s1 = conv_w -> copy_zero; main = scan ->
        // conv_a -> (wait conv_w) gemm -> attn; join copy at the end.
        cudaEventRecord(eFork, 0);
        cudaStreamWaitEvent(s1, eFork, 0);
        conv_w<<<Nc, 128, 0, s1>>>(wqk);
        cudaEventRecord(eW, s1);
        copy_zero<<<Bc * Sc, 256, 0, s1>>>(emb, sidx, out);
        cudaEventRecord(eJoin, s1);

        scan_groups<<<2, 1024>>>(sidx, bias);
        conv_a<<<Mc / 4, 128>>>(emb);

        cudaStreamWaitEvent(0, eW, 0);
        dim3 gg(16, NTILES);
        gemm_qk<<<gg, 256, SMEM_TOT>>>(bias);

        attn_final<<<Lc, 128>>>(emb, sidx, out);
        cudaStreamWaitEvent(0, eJoin, 0);
    } else {
        // serial fallback
        conv_w<<<Nc, 128>>>(wqk);
        copy_zero<<<Bc * Sc, 256>>>(emb, sidx, out);
        scan_groups<<<2, 1024>>>(sidx, bias);
        conv_a<<<Mc / 4, 128>>>(emb);
        dim3 gg(16, NTILES);
        gemm_qk<<<gg, 256, SMEM_TOT>>>(bias);
        attn_final<<<Lc, 128>>>(emb, sidx, out);
    }
}